// round 1
// baseline (speedup 1.0000x reference)
#include <cuda_runtime.h>

#define NROWS 2048
#define KDIM  1024
#define KCLI  64

// -------- device scratch (no allocations allowed) --------
static __device__ float g_im[NROWS * KDIM];     // normalized phi_im
static __device__ float g_cli[NROWS * KCLI];    // normalized phi_cli
static __device__ unsigned char g_cls[NROWS];   // bit0: m0, bit1: m1, bit2: m2
static __device__ unsigned long long g_min6[6]; // packed (orderedFloat<<32)|flatidx

// ordered-float encoding: monotone map float -> uint32 so integer min == float min
__device__ __forceinline__ unsigned f2o(float f) {
    unsigned u = __float_as_uint(f);
    return (u & 0x80000000u) ? ~u : (u | 0x80000000u);
}
__device__ __forceinline__ float o2f(unsigned o) {
    unsigned u = (o & 0x80000000u) ? (o & 0x7fffffffu) : ~o;
    return __uint_as_float(u);
}
#define INF_KEY 0xFF80000000000000ull  // (+inf ordered)<<32 | 0

// ---------------------------------------------------------------------------
// prep: detect int64-vs-int32 layout of t/traumatic, build class bits, init mins
// ---------------------------------------------------------------------------
__global__ void prep_kernel(const int* __restrict__ tw, const int* __restrict__ trw) {
    __shared__ int acc[256];
    int tid = threadIdx.x;
    // If t is int64, values in [0,3) => every odd 32-bit word (high half) is 0.
    // If t is int32, odd words are t-values (P(all zero) ~ (1/3)^2048 == never).
    int o = 0;
    for (int i = tid; i < NROWS; i += 256) o |= tw[2 * i + 1];
    acc[tid] = o;
    __syncthreads();
    for (int s = 128; s > 0; s >>= 1) {
        if (tid < s) acc[tid] |= acc[tid + s];
        __syncthreads();
    }
    bool is64 = (acc[0] == 0);

    int gid = blockIdx.x * 256 + tid;
    if (gid < 6) g_min6[gid] = INF_KEY;

    for (int i = gid; i < NROWS; i += gridDim.x * 256) {
        // t shape (N,2) row-major: element (i,1) is flat element 2*i+1
        int t1 = is64 ? tw[4 * i + 2] : tw[2 * i + 1];  // low word of int64
        int tr = is64 ? trw[2 * i]    : trw[i];
        unsigned char c = 0;
        if (t1 == 0 && tr == 1) c |= 1;  // m0
        if (t1 == 1)            c |= 2;  // m1
        if (t1 == 2)            c |= 4;  // m2
        g_cls[i] = c;
    }
}

// ---------------------------------------------------------------------------
// row L2-normalization of both feature matrices (block = one row)
// ---------------------------------------------------------------------------
__global__ void norm_kernel(const float* __restrict__ im, const float* __restrict__ cli) {
    int row = blockIdx.x, tid = threadIdx.x;
    __shared__ float red[256];

    // phi_im row: 1024 floats = 256 float4, one per thread
    float4 v = ((const float4*)(im + (size_t)row * KDIM))[tid];
    red[tid] = v.x * v.x + v.y * v.y + v.z * v.z + v.w * v.w;
    __syncthreads();
    for (int s = 128; s > 0; s >>= 1) {
        if (tid < s) red[tid] += red[tid + s];
        __syncthreads();
    }
    float inv = 1.0f / fmaxf(sqrtf(red[0]), 1e-12f);
    float4 w;
    w.x = v.x * inv; w.y = v.y * inv; w.z = v.z * inv; w.w = v.w * inv;
    ((float4*)(g_im + (size_t)row * KDIM))[tid] = w;
    __syncthreads();

    // phi_cli row: 64 floats
    float c = (tid < KCLI) ? cli[row * KCLI + tid] : 0.0f;
    red[tid] = c * c;
    __syncthreads();
    for (int s = 128; s > 0; s >>= 1) {
        if (tid < s) red[tid] += red[tid + s];
        __syncthreads();
    }
    float inv2 = 1.0f / fmaxf(sqrtf(red[0]), 1e-12f);
    if (tid < KCLI) g_cli[row * KCLI + tid] = c * inv2;
}

// ---------------------------------------------------------------------------
// fused SGEMM (S = A A^T tile) + 3 masked matrix writes + packed argmin
// BM=BN=128, BK=16, 256 threads, 8x8 micro-tile per thread
// ---------------------------------------------------------------------------
template <int K>
__global__ __launch_bounds__(256)
void gemm_masked(float* __restrict__ out, int pairBase) {
    const float* __restrict__ A = (K == KDIM) ? g_im : g_cli;

    __shared__ float As[16][128];  // [k][row]
    __shared__ float Bs[16][128];  // [k][col]

    const int rowBase = blockIdx.y * 128;
    const int colBase = blockIdx.x * 128;
    const int tid = threadIdx.x;
    const int tx = tid & 15;   // 16 col-groups
    const int ty = tid >> 4;   // 16 row-groups

    float acc[8][8];
#pragma unroll
    for (int i = 0; i < 8; i++)
#pragma unroll
        for (int j = 0; j < 8; j++) acc[i][j] = 0.0f;

    // loader mapping: 512 float4 per tile, 2 per thread
    const int lr0 = tid >> 2;        // row 0..63 (and +64)
    const int lk0 = (tid & 3) * 4;   // k offset 0,4,8,12

    for (int kt = 0; kt < K; kt += 16) {
        float4 a0 = *(const float4*)&A[(size_t)(rowBase + lr0)      * K + kt + lk0];
        float4 a1 = *(const float4*)&A[(size_t)(rowBase + lr0 + 64) * K + kt + lk0];
        float4 b0 = *(const float4*)&A[(size_t)(colBase + lr0)      * K + kt + lk0];
        float4 b1 = *(const float4*)&A[(size_t)(colBase + lr0 + 64) * K + kt + lk0];
        __syncthreads();
        As[lk0 + 0][lr0] = a0.x; As[lk0 + 1][lr0] = a0.y;
        As[lk0 + 2][lr0] = a0.z; As[lk0 + 3][lr0] = a0.w;
        As[lk0 + 0][lr0 + 64] = a1.x; As[lk0 + 1][lr0 + 64] = a1.y;
        As[lk0 + 2][lr0 + 64] = a1.z; As[lk0 + 3][lr0 + 64] = a1.w;
        Bs[lk0 + 0][lr0] = b0.x; Bs[lk0 + 1][lr0] = b0.y;
        Bs[lk0 + 2][lr0] = b0.z; Bs[lk0 + 3][lr0] = b0.w;
        Bs[lk0 + 0][lr0 + 64] = b1.x; Bs[lk0 + 1][lr0 + 64] = b1.y;
        Bs[lk0 + 2][lr0 + 64] = b1.z; Bs[lk0 + 3][lr0 + 64] = b1.w;
        __syncthreads();

#pragma unroll
        for (int k = 0; k < 16; k++) {
            float4 ar0 = *(const float4*)&As[k][ty * 8];
            float4 ar1 = *(const float4*)&As[k][ty * 8 + 4];
            float4 br0 = *(const float4*)&Bs[k][tx * 8];
            float4 br1 = *(const float4*)&Bs[k][tx * 8 + 4];
            float a[8] = {ar0.x, ar0.y, ar0.z, ar0.w, ar1.x, ar1.y, ar1.z, ar1.w};
            float b[8] = {br0.x, br0.y, br0.z, br0.w, br1.x, br1.y, br1.z, br1.w};
#pragma unroll
            for (int i = 0; i < 8; i++)
#pragma unroll
                for (int j = 0; j < 8; j++) acc[i][j] = fmaf(a[i], b[j], acc[i][j]);
        }
    }

    // ---- epilogue: masked writes + packed argmin ----
    unsigned char cr[8], cc[8];
#pragma unroll
    for (int i = 0; i < 8; i++) {
        cr[i] = g_cls[rowBase + ty * 8 + i];
        cc[i] = g_cls[colBase + tx * 8 + i];
    }
    const unsigned char rb[3] = {1, 1, 2};  // row class bit per pair
    const unsigned char cb[3] = {2, 4, 4};  // col class bit per pair
    unsigned long long best[3] = {INF_KEY, INF_KEY, INF_KEY};

#pragma unroll
    for (int p = 0; p < 3; p++) {
        float* op = out + (size_t)(pairBase + p) * (size_t)NROWS * NROWS;
#pragma unroll
        for (int ii = 0; ii < 8; ii++) {
            int gr = rowBase + ty * 8 + ii;
            bool rv = (cr[ii] & rb[p]) != 0;
            float w[8];
#pragma unroll
            for (int jj = 0; jj < 8; jj++) {
                bool v = rv && ((cc[jj] & cb[p]) != 0);
                float s = acc[ii][jj];
                w[jj] = v ? s : 0.0f;
                if (v) {
                    unsigned flat = (unsigned)gr * NROWS + (unsigned)(colBase + tx * 8 + jj);
                    unsigned long long key = ((unsigned long long)f2o(s) << 32) | flat;
                    if (key < best[p]) best[p] = key;
                }
            }
            float4* dst = (float4*)(op + (size_t)gr * NROWS + colBase + tx * 8);
            dst[0] = make_float4(w[0], w[1], w[2], w[3]);
            dst[1] = make_float4(w[4], w[5], w[6], w[7]);
        }
    }

    // warp-reduce mins, one atomic per warp per pair
#pragma unroll
    for (int p = 0; p < 3; p++) {
        unsigned long long b = best[p];
#pragma unroll
        for (int off = 16; off > 0; off >>= 1) {
            unsigned long long o = __shfl_down_sync(0xffffffffu, b, off);
            if (o < b) b = o;
        }
        if ((tid & 31) == 0 && b != INF_KEY)
            atomicMin(&g_min6[pairBase + p], b);
    }
}

// ---------------------------------------------------------------------------
// finalize: unpack 6 mins into tail of output
// ---------------------------------------------------------------------------
__global__ void finalize_kernel(float* __restrict__ out) {
    int p = threadIdx.x;
    if (p < 6) {
        unsigned long long k = g_min6[p];
        size_t base = (size_t)6 * NROWS * NROWS;
        out[base + p] = o2f((unsigned)(k >> 32));
        unsigned flat = (unsigned)k;
        out[base + 6 + 2 * p]     = (float)(flat / NROWS);
        out[base + 6 + 2 * p + 1] = (float)(flat % NROWS);
    }
}

// ---------------------------------------------------------------------------
extern "C" void kernel_launch(void* const* d_in, const int* in_sizes, int n_in,
                              void* d_out, int out_size) {
    const float* phi_im  = (const float*)d_in[0];
    const float* phi_cli = (const float*)d_in[1];
    const int*   tw      = (const int*)d_in[2];
    const int*   trw     = (const int*)d_in[3];
    float* out = (float*)d_out;

    prep_kernel<<<8, 256>>>(tw, trw);
    norm_kernel<<<NROWS, 256>>>(phi_im, phi_cli);

    dim3 grid(16, 16);
    gemm_masked<KDIM><<<grid, 256>>>(out, 0);
    gemm_masked<KCLI><<<grid, 256>>>(out, 3);

    finalize_kernel<<<1, 32>>>(out);
}

// round 4
// speedup vs baseline: 1.5614x; 1.5614x over previous
#include <cuda_runtime.h>

#define NROWS 2048
#define KDIM  1024
#define KCLI  64
#define PADROWS (NROWS + 64)   // +64: tile loader may over-read past last class

// -------- device scratch (statics: no runtime allocation allowed) --------
static __device__ float g_gim[PADROWS * KDIM];   // gathered normalized phi_im (classes concatenated)
static __device__ float g_gcli[PADROWS * KCLI];  // gathered normalized phi_cli
static __device__ int   g_rows[NROWS];           // global slot -> original row index
static __device__ int   g_cnt[3];                // class sizes
static __device__ int   g_off[3];                // class start offsets in gathered buffers
static __device__ int   g_cursor[3];             // slot-assignment cursors
static __device__ int   g_cid[NROWS];            // row -> class (-1 if none)
static __device__ int   g_slot[NROWS];           // row -> global slot
static __device__ unsigned long long g_min6[6];  // packed (orderedFloat<<32)|flat

// ordered-float: monotone float->uint32 so integer min == float min
__device__ __forceinline__ unsigned f2o(float f) {
    unsigned u = __float_as_uint(f);
    return (u & 0x80000000u) ? ~u : (u | 0x80000000u);
}
__device__ __forceinline__ float o2f(unsigned o) {
    unsigned u = (o & 0x80000000u) ? (o & 0x7fffffffu) : ~o;
    return __uint_as_float(u);
}
#define INF_KEY 0xFF80000000000000ull

// ---------------------------------------------------------------------------
// prep (single block): detect int64/int32 layout, reset state, classify rows,
// build concatenated class lists with per-class offsets
// ---------------------------------------------------------------------------
__global__ void prep_kernel(const int* __restrict__ tw, const int* __restrict__ trw) {
    __shared__ int acc[256];
    int tid = threadIdx.x;
    if (tid < 6) g_min6[tid] = INF_KEY;
    if (tid < 3) g_cnt[tid] = 0;

    // int64 detection: t values in [0,3) => all odd 32-bit words zero iff int64
    int o = 0;
    for (int i = tid; i < NROWS; i += 256) o |= tw[2 * i + 1];
    acc[tid] = o;
    __syncthreads();
    for (int s = 128; s > 0; s >>= 1) {
        if (tid < s) acc[tid] |= acc[tid + s];
        __syncthreads();
    }
    bool is64 = (acc[0] == 0);

    // pass 1: classify + count
    for (int i = tid; i < NROWS; i += 256) {
        int t1 = is64 ? tw[4 * i + 2] : tw[2 * i + 1];
        int tr = is64 ? trw[2 * i]    : trw[i];
        int c = -1;
        if (t1 == 0 && tr == 1) c = 0;   // m0
        else if (t1 == 1)       c = 1;   // m1
        else if (t1 == 2)       c = 2;   // m2
        g_cid[i] = c;
        if (c >= 0) atomicAdd(&g_cnt[c], 1);
    }
    __syncthreads();

    if (tid == 0) {
        g_off[0] = 0;
        g_off[1] = g_cnt[0];
        g_off[2] = g_cnt[0] + g_cnt[1];
        g_cursor[0] = g_off[0];
        g_cursor[1] = g_off[1];
        g_cursor[2] = g_off[2];
    }
    __syncthreads();

    // pass 2: assign global slots
    for (int i = tid; i < NROWS; i += 256) {
        int c = g_cid[i];
        if (c >= 0) {
            int s2 = atomicAdd(&g_cursor[c], 1);
            g_rows[s2] = i;
            g_slot[i] = s2;
        }
    }
}

// ---------------------------------------------------------------------------
// normalize + gather: one block per row; rows without a class skip all work
// ---------------------------------------------------------------------------
__global__ void norm_gather(const float* __restrict__ im, const float* __restrict__ cli) {
    int row = blockIdx.x;
    int c = g_cid[row];
    if (c < 0) return;
    int slot = g_slot[row];
    int tid = threadIdx.x;
    __shared__ float red[256];

    float4 v = ((const float4*)(im + (size_t)row * KDIM))[tid];
    red[tid] = v.x * v.x + v.y * v.y + v.z * v.z + v.w * v.w;
    __syncthreads();
    for (int s = 128; s > 0; s >>= 1) {
        if (tid < s) red[tid] += red[tid + s];
        __syncthreads();
    }
    float inv = 1.0f / fmaxf(sqrtf(red[0]), 1e-12f);
    float4 w = make_float4(v.x * inv, v.y * inv, v.z * inv, v.w * inv);
    ((float4*)(g_gim + (size_t)slot * KDIM))[tid] = w;
    __syncthreads();

    float cv = (tid < KCLI) ? cli[row * KCLI + tid] : 0.0f;
    red[tid] = cv * cv;
    __syncthreads();
    for (int s = 128; s > 0; s >>= 1) {
        if (tid < s) red[tid] += red[tid + s];
        __syncthreads();
    }
    float inv2 = 1.0f / fmaxf(sqrtf(red[0]), 1e-12f);
    if (tid < KCLI) g_gcli[slot * KCLI + tid] = cv * inv2;
}

// ---------------------------------------------------------------------------
// zero the whole output buffer (poisoned by harness; valid cells written later)
// ---------------------------------------------------------------------------
__global__ void zero_out(float* __restrict__ out, int n) {
    int stride = gridDim.x * blockDim.x;
    int n4 = n / 4;
    for (int i = blockIdx.x * blockDim.x + threadIdx.x; i < n4; i += stride)
        ((float4*)out)[i] = make_float4(0.f, 0.f, 0.f, 0.f);
    int tail = n4 * 4 + blockIdx.x * blockDim.x + threadIdx.x;
    if (tail < n) out[tail] = 0.f;
}

// ---------------------------------------------------------------------------
// compacted rectangular SGEMM + scatter + argmin.
// 6 combos: (im,cli) x class-pairs (0,1),(0,2),(1,2). 64x64 tiles, BK=16,
// 256 threads, 4x4 micro-tile. Grid = 6*32*32 blocks, early-exit on bounds.
// Over-reads past a class range hit the next class / 64-row pad (valid memory);
// epilogue bound guards discard those results.
// ---------------------------------------------------------------------------
__global__ __launch_bounds__(256)
void gemm_all(float* __restrict__ out) {
    const int combo = blockIdx.x >> 10;         // 0..5
    const int t = blockIdx.x & 1023;
    const int by = t >> 5, bx = t & 31;         // 32x32 tile grid of 64

    const int cAtab[6] = {0, 0, 1, 0, 0, 1};
    const int cBtab[6] = {1, 2, 2, 1, 2, 2};
    const int ca = cAtab[combo], cb = cBtab[combo];
    const int na = g_cnt[ca], nb = g_cnt[cb];
    if (by * 64 >= na || bx * 64 >= nb) return;
    const int offA = g_off[ca], offB = g_off[cb];

    const bool isIm = combo < 3;
    const int K = isIm ? KDIM : KCLI;
    const float* __restrict__ A = (isIm ? g_gim : g_gcli) + (size_t)offA * K;
    const float* __restrict__ B = (isIm ? g_gim : g_gcli) + (size_t)offB * K;

    __shared__ float As[16][72];  // pad 72: STS transpose + LDS.128 conflict-free
    __shared__ float Bs[16][72];

    const int tid = threadIdx.x;
    const int tx = tid & 15;      // col group
    const int ty = tid >> 4;      // row group
    const int lr = tid >> 2;      // loader row 0..63
    const int lk = (tid & 3) * 4; // loader k offset

    const size_t rowA = (size_t)(by * 64 + lr) * K;
    const size_t rowB = (size_t)(bx * 64 + lr) * K;

    float acc[4][4];
#pragma unroll
    for (int i = 0; i < 4; i++)
#pragma unroll
        for (int j = 0; j < 4; j++) acc[i][j] = 0.0f;

    for (int kt = 0; kt < K; kt += 16) {
        float4 a = *(const float4*)&A[rowA + kt + lk];
        float4 b = *(const float4*)&B[rowB + kt + lk];
        __syncthreads();
        As[lk + 0][lr] = a.x; As[lk + 1][lr] = a.y;
        As[lk + 2][lr] = a.z; As[lk + 3][lr] = a.w;
        Bs[lk + 0][lr] = b.x; Bs[lk + 1][lr] = b.y;
        Bs[lk + 2][lr] = b.z; Bs[lk + 3][lr] = b.w;
        __syncthreads();

#pragma unroll
        for (int k = 0; k < 16; k++) {
            float4 av = *(const float4*)&As[k][ty * 4];
            float4 bv = *(const float4*)&Bs[k][tx * 4];
            float aa[4] = {av.x, av.y, av.z, av.w};
            float bb[4] = {bv.x, bv.y, bv.z, bv.w};
#pragma unroll
            for (int i = 0; i < 4; i++)
#pragma unroll
                for (int j = 0; j < 4; j++)
                    acc[i][j] = fmaf(aa[i], bb[j], acc[i][j]);
        }
    }

    // ---- epilogue: scatter valid entries + packed argmin ----
    int gr[4], gc[4];
    bool rv[4], cv[4];
#pragma unroll
    for (int i = 0; i < 4; i++) {
        int r = by * 64 + ty * 4 + i;
        rv[i] = r < na;
        gr[i] = rv[i] ? g_rows[offA + r] : 0;
    }
#pragma unroll
    for (int j = 0; j < 4; j++) {
        int c = bx * 64 + tx * 4 + j;
        cv[j] = c < nb;
        gc[j] = cv[j] ? g_rows[offB + c] : 0;
    }

    float* __restrict__ op = out + (size_t)combo * NROWS * NROWS;
    unsigned long long best = INF_KEY;
#pragma unroll
    for (int i = 0; i < 4; i++) {
        if (!rv[i]) continue;
        unsigned rbase = (unsigned)gr[i] * NROWS;
#pragma unroll
        for (int j = 0; j < 4; j++) {
            if (!cv[j]) continue;
            float s = acc[i][j];
            unsigned flat = rbase + (unsigned)gc[j];
            op[flat] = s;
            unsigned long long key = ((unsigned long long)f2o(s) << 32) | flat;
            if (key < best) best = key;
        }
    }

#pragma unroll
    for (int off = 16; off > 0; off >>= 1) {
        unsigned long long o = __shfl_down_sync(0xffffffffu, best, off);
        if (o < best) best = o;
    }
    if ((tid & 31) == 0 && best != INF_KEY)
        atomicMin(&g_min6[combo], best);
}

// ---------------------------------------------------------------------------
__global__ void finalize_kernel(float* __restrict__ out) {
    int p = threadIdx.x;
    if (p < 6) {
        unsigned long long k = g_min6[p];
        size_t base = (size_t)6 * NROWS * NROWS;
        out[base + p] = o2f((unsigned)(k >> 32));
        unsigned flat = (unsigned)k;
        out[base + 6 + 2 * p]     = (float)(flat / NROWS);
        out[base + 6 + 2 * p + 1] = (float)(flat % NROWS);
    }
}

// ---------------------------------------------------------------------------
extern "C" void kernel_launch(void* const* d_in, const int* in_sizes, int n_in,
                              void* d_out, int out_size) {
    const float* phi_im  = (const float*)d_in[0];
    const float* phi_cli = (const float*)d_in[1];
    const int*   tw      = (const int*)d_in[2];
    const int*   trw     = (const int*)d_in[3];
    float* out = (float*)d_out;

    prep_kernel<<<1, 256>>>(tw, trw);
    norm_gather<<<NROWS, 256>>>(phi_im, phi_cli);

    zero_out<<<1024, 256>>>(out, out_size);

    gemm_all<<<6 * 32 * 32, 256>>>(out);

    finalize_kernel<<<1, 32>>>(out);
}

// round 8
// speedup vs baseline: 1.7446x; 1.1174x over previous
#include <cuda_runtime.h>

#define NROWS 2048
#define KDIM  1024
#define KCLI  64
#define PADROWS (NROWS + 128)   // tile loader may over-read past last class

// -------- device scratch (statics kept at the ~9.5MB profile that passes) ----
static __device__ float g_gim[PADROWS * KDIM];    // gathered normalized phi_im
static __device__ float g_gcli[PADROWS * KCLI];   // gathered normalized phi_cli
static __device__ int   g_rows[NROWS];            // global slot -> original row
static __device__ int   g_cnt[3], g_off[3], g_cursor[3];
static __device__ int   g_cid[NROWS], g_slot[NROWS];
static __device__ unsigned long long g_min6[6];

__device__ __forceinline__ unsigned f2o(float f) {
    unsigned u = __float_as_uint(f);
    return (u & 0x80000000u) ? ~u : (u | 0x80000000u);
}
__device__ __forceinline__ float o2f(unsigned o) {
    unsigned u = (o & 0x80000000u) ? (o & 0x7fffffffu) : ~o;
    return __uint_as_float(u);
}
#define INF_KEY 0xFF80000000000000ull

__device__ __constant__ int c_cA[3] = {0, 0, 1};
__device__ __constant__ int c_cB[3] = {1, 2, 2};

// ---------------------------------------------------------------------------
__global__ void prep_kernel(const int* __restrict__ tw, const int* __restrict__ trw) {
    __shared__ int acc[256];
    int tid = threadIdx.x;
    if (tid < 6) g_min6[tid] = INF_KEY;
    if (tid < 3) g_cnt[tid] = 0;

    // int64 vs int32 layout detection (t values in [0,3))
    int o = 0;
    for (int i = tid; i < NROWS; i += 256) o |= tw[2 * i + 1];
    acc[tid] = o;
    __syncthreads();
    for (int s = 128; s > 0; s >>= 1) {
        if (tid < s) acc[tid] |= acc[tid + s];
        __syncthreads();
    }
    bool is64 = (acc[0] == 0);

    for (int i = tid; i < NROWS; i += 256) {
        int t1 = is64 ? tw[4 * i + 2] : tw[2 * i + 1];
        int tr = is64 ? trw[2 * i]    : trw[i];
        int c = -1;
        if (t1 == 0 && tr == 1) c = 0;
        else if (t1 == 1)       c = 1;
        else if (t1 == 2)       c = 2;
        g_cid[i] = c;
        if (c >= 0) atomicAdd(&g_cnt[c], 1);
    }
    __syncthreads();

    if (tid == 0) {
        g_off[0] = 0; g_off[1] = g_cnt[0]; g_off[2] = g_cnt[0] + g_cnt[1];
        g_cursor[0] = g_off[0]; g_cursor[1] = g_off[1]; g_cursor[2] = g_off[2];
    }
    __syncthreads();

    for (int i = tid; i < NROWS; i += 256) {
        int c = g_cid[i];
        if (c >= 0) {
            int s2 = atomicAdd(&g_cursor[c], 1);
            g_rows[s2] = i;
            g_slot[i] = s2;
        }
    }
}

// ---------------------------------------------------------------------------
__global__ void norm_gather(const float* __restrict__ im, const float* __restrict__ cli) {
    int row = blockIdx.x;
    int c = g_cid[row];
    if (c < 0) return;
    int slot = g_slot[row];
    int tid = threadIdx.x;
    __shared__ float red[256];

    float4 v = ((const float4*)(im + (size_t)row * KDIM))[tid];
    red[tid] = v.x * v.x + v.y * v.y + v.z * v.z + v.w * v.w;
    __syncthreads();
    for (int s = 128; s > 0; s >>= 1) {
        if (tid < s) red[tid] += red[tid + s];
        __syncthreads();
    }
    float inv = 1.0f / fmaxf(sqrtf(red[0]), 1e-12f);
    ((float4*)(g_gim + (size_t)slot * KDIM))[tid] =
        make_float4(v.x * inv, v.y * inv, v.z * inv, v.w * inv);
    __syncthreads();

    float cv = (tid < KCLI) ? cli[row * KCLI + tid] : 0.0f;
    red[tid] = cv * cv;
    __syncthreads();
    for (int s = 128; s > 0; s >>= 1) {
        if (tid < s) red[tid] += red[tid + s];
        __syncthreads();
    }
    float inv2 = 1.0f / fmaxf(sqrtf(red[0]), 1e-12f);
    if (tid < KCLI) g_gcli[slot * KCLI + tid] = cv * inv2;
}

// ---------------------------------------------------------------------------
__global__ void zero_out(float* __restrict__ out, int n) {
    int stride = gridDim.x * blockDim.x;
    int n4 = n / 4;
    for (int i = blockIdx.x * blockDim.x + threadIdx.x; i < n4; i += stride)
        ((float4*)out)[i] = make_float4(0.f, 0.f, 0.f, 0.f);
    int tail = n4 * 4 + blockIdx.x * blockDim.x + threadIdx.x;
    if (tail < n) out[tail] = 0.f;
}

// ---------------------------------------------------------------------------
// 128x128 tile, 8x8 micro, 256 threads — near-roofline FFMA engine
// ---------------------------------------------------------------------------
__device__ __forceinline__ void tile_gemm(
    const float* __restrict__ A, const float* __restrict__ B, int K,
    int kbeg, int kend, float (&acc)[8][8],
    float (*As)[128], float (*Bs)[128], int tid)
{
    const int lr0 = tid >> 2;
    const int lk0 = (tid & 3) * 4;
    const int tx = tid & 15;
    const int ty = tid >> 4;

    for (int kt = kbeg; kt < kend; kt += 16) {
        float4 a0 = *(const float4*)&A[(size_t)lr0        * K + kt + lk0];
        float4 a1 = *(const float4*)&A[(size_t)(lr0 + 64) * K + kt + lk0];
        float4 b0 = *(const float4*)&B[(size_t)lr0        * K + kt + lk0];
        float4 b1 = *(const float4*)&B[(size_t)(lr0 + 64) * K + kt + lk0];
        __syncthreads();
        As[lk0 + 0][lr0] = a0.x; As[lk0 + 1][lr0] = a0.y;
        As[lk0 + 2][lr0] = a0.z; As[lk0 + 3][lr0] = a0.w;
        As[lk0 + 0][lr0 + 64] = a1.x; As[lk0 + 1][lr0 + 64] = a1.y;
        As[lk0 + 2][lr0 + 64] = a1.z; As[lk0 + 3][lr0 + 64] = a1.w;
        Bs[lk0 + 0][lr0] = b0.x; Bs[lk0 + 1][lr0] = b0.y;
        Bs[lk0 + 2][lr0] = b0.z; Bs[lk0 + 3][lr0] = b0.w;
        Bs[lk0 + 0][lr0 + 64] = b1.x; Bs[lk0 + 1][lr0 + 64] = b1.y;
        Bs[lk0 + 2][lr0 + 64] = b1.z; Bs[lk0 + 3][lr0 + 64] = b1.w;
        __syncthreads();

#pragma unroll
        for (int k = 0; k < 16; k++) {
            float4 ar0 = *(const float4*)&As[k][ty * 8];
            float4 ar1 = *(const float4*)&As[k][ty * 8 + 4];
            float4 br0 = *(const float4*)&Bs[k][tx * 8];
            float4 br1 = *(const float4*)&Bs[k][tx * 8 + 4];
            float a[8] = {ar0.x, ar0.y, ar0.z, ar0.w, ar1.x, ar1.y, ar1.z, ar1.w};
            float b[8] = {br0.x, br0.y, br0.z, br0.w, br1.x, br1.y, br1.z, br1.w};
#pragma unroll
            for (int i = 0; i < 8; i++)
#pragma unroll
                for (int j = 0; j < 8; j++) acc[i][j] = fmaf(a[i], b[j], acc[i][j]);
        }
    }
}

// ---------------------------------------------------------------------------
// z in [0,6): im GEMM, combo=z>>1, split=z&1 -> atomicAdd into zeroed out.
//   Exactly 2 addends per cell on a 0-initialized cell => bitwise deterministic
//   (fp add is commutative; only order of the two adds can vary).
// z in [6,9): cli GEMM (K=64) -> direct store + argmin.
// ---------------------------------------------------------------------------
__global__ __launch_bounds__(256)
void gemm_all(float* __restrict__ out) {
    __shared__ float As[16][128];
    __shared__ float Bs[16][128];
    const int tid = threadIdx.x;
    const int z = blockIdx.z;
    const int bx = blockIdx.x, by = blockIdx.y;
    const int tx = tid & 15, ty = tid >> 4;

    float acc[8][8];
#pragma unroll
    for (int i = 0; i < 8; i++)
#pragma unroll
        for (int j = 0; j < 8; j++) acc[i][j] = 0.0f;

    if (z < 6) {
        const int combo = z >> 1, split = z & 1;
        const int ca = c_cA[combo], cb = c_cB[combo];
        const int na = g_cnt[ca], nb = g_cnt[cb];
        if (by * 128 >= na || bx * 128 >= nb) return;

        const float* A = g_gim + (size_t)(g_off[ca] + by * 128) * KDIM;
        const float* B = g_gim + (size_t)(g_off[cb] + bx * 128) * KDIM;
        tile_gemm(A, B, KDIM, split * 512, split * 512 + 512, acc, As, Bs, tid);

        const int offA = g_off[ca], offB = g_off[cb];
        int gc[8]; bool cv[8];
#pragma unroll
        for (int j = 0; j < 8; j++) {
            int c = bx * 128 + tx * 8 + j;
            cv[j] = c < nb;
            gc[j] = cv[j] ? g_rows[offB + c] : 0;
        }
        float* __restrict__ op = out + (size_t)combo * NROWS * NROWS;
#pragma unroll
        for (int i = 0; i < 8; i++) {
            int r = by * 128 + ty * 8 + i;
            if (r >= na) continue;
            unsigned rbase = (unsigned)g_rows[offA + r] * NROWS;
#pragma unroll
            for (int j = 0; j < 8; j++) {
                if (!cv[j]) continue;
                atomicAdd(&op[rbase + (unsigned)gc[j]], acc[i][j]);
            }
        }
    } else {
        const int combo = z - 6;
        const int ca = c_cA[combo], cb = c_cB[combo];
        const int na = g_cnt[ca], nb = g_cnt[cb];
        if (by * 128 >= na || bx * 128 >= nb) return;

        const float* A = g_gcli + (size_t)(g_off[ca] + by * 128) * KCLI;
        const float* B = g_gcli + (size_t)(g_off[cb] + bx * 128) * KCLI;
        tile_gemm(A, B, KCLI, 0, KCLI, acc, As, Bs, tid);

        const int offA = g_off[ca], offB = g_off[cb];
        int gc[8]; bool cv[8];
#pragma unroll
        for (int j = 0; j < 8; j++) {
            int c = bx * 128 + tx * 8 + j;
            cv[j] = c < nb;
            gc[j] = cv[j] ? g_rows[offB + c] : 0;
        }
        float* __restrict__ op = out + (size_t)(3 + combo) * NROWS * NROWS;
        unsigned long long best = INF_KEY;
#pragma unroll
        for (int i = 0; i < 8; i++) {
            int r = by * 128 + ty * 8 + i;
            if (r >= na) continue;
            unsigned rbase = (unsigned)g_rows[offA + r] * NROWS;
#pragma unroll
            for (int j = 0; j < 8; j++) {
                if (!cv[j]) continue;
                float s = acc[i][j];
                unsigned flat = rbase + (unsigned)gc[j];
                op[flat] = s;
                unsigned long long key = ((unsigned long long)f2o(s) << 32) | flat;
                if (key < best) best = key;
            }
        }
#pragma unroll
        for (int off = 16; off > 0; off >>= 1) {
            unsigned long long o = __shfl_down_sync(0xffffffffu, best, off);
            if (o < best) best = o;
        }
        if ((tid & 31) == 0 && best != INF_KEY)
            atomicMin(&g_min6[3 + combo], best);
    }
}

// ---------------------------------------------------------------------------
// argmin over the summed im-combo cells (reads deterministic final values)
// ---------------------------------------------------------------------------
__global__ __launch_bounds__(256)
void argmin_im(const float* __restrict__ out) {
    const int combo = blockIdx.z;
    const int ca = c_cA[combo], cb = c_cB[combo];
    const int na = g_cnt[ca], nb = g_cnt[cb];
    const int bx = blockIdx.x, by = blockIdx.y;
    if (by * 128 >= na || bx * 128 >= nb) return;

    const int offA = g_off[ca], offB = g_off[cb];
    const int tid = threadIdx.x;
    const int tx = tid & 15, ty = tid >> 4;

    int gc[8]; bool cv[8];
#pragma unroll
    for (int j = 0; j < 8; j++) {
        int c = bx * 128 + tx * 8 + j;
        cv[j] = c < nb;
        gc[j] = cv[j] ? g_rows[offB + c] : 0;
    }

    const float* __restrict__ op = out + (size_t)combo * NROWS * NROWS;
    unsigned long long best = INF_KEY;
#pragma unroll
    for (int i = 0; i < 8; i++) {
        int r = by * 128 + ty * 8 + i;
        if (r >= na) continue;
        unsigned rbase = (unsigned)g_rows[offA + r] * NROWS;
#pragma unroll
        for (int j = 0; j < 8; j++) {
            if (!cv[j]) continue;
            unsigned flat = rbase + (unsigned)gc[j];
            float s = op[flat];
            unsigned long long key = ((unsigned long long)f2o(s) << 32) | flat;
            if (key < best) best = key;
        }
    }
#pragma unroll
    for (int off = 16; off > 0; off >>= 1) {
        unsigned long long o = __shfl_down_sync(0xffffffffu, best, off);
        if (o < best) best = o;
    }
    if ((tid & 31) == 0 && best != INF_KEY)
        atomicMin(&g_min6[combo], best);
}

// ---------------------------------------------------------------------------
__global__ void finalize_kernel(float* __restrict__ out) {
    int p = threadIdx.x;
    if (p < 6) {
        unsigned long long k = g_min6[p];
        size_t base = (size_t)6 * NROWS * NROWS;
        out[base + p] = o2f((unsigned)(k >> 32));
        unsigned flat = (unsigned)k;
        out[base + 6 + 2 * p]     = (float)(flat / NROWS);
        out[base + 6 + 2 * p + 1] = (float)(flat % NROWS);
    }
}

// ---------------------------------------------------------------------------
extern "C" void kernel_launch(void* const* d_in, const int* in_sizes, int n_in,
                              void* d_out, int out_size) {
    const float* phi_im  = (const float*)d_in[0];
    const float* phi_cli = (const float*)d_in[1];
    const int*   tw      = (const int*)d_in[2];
    const int*   trw     = (const int*)d_in[3];
    float* out = (float*)d_out;

    prep_kernel<<<1, 256>>>(tw, trw);
    norm_gather<<<NROWS, 256>>>(phi_im, phi_cli);
    zero_out<<<2048, 256>>>(out, out_size);

    dim3 ggrid(6, 6, 9);
    gemm_all<<<ggrid, 256>>>(out);

    dim3 agrid(6, 6, 3);
    argmin_im<<<agrid, 256>>>(out);

    finalize_kernel<<<1, 32>>>(out);
}

// round 11
// speedup vs baseline: 2.1219x; 1.2163x over previous
#include <cuda_runtime.h>

#define NROWS 2048
#define KDIM  1024
#define KCLI  64
#define PADROWS (NROWS + 128)   // tile loader may over-read past last class

// -------- device scratch (statics kept at the ~9.5MB profile that passes) ----
static __device__ float g_gim[PADROWS * KDIM];    // gathered normalized phi_im
static __device__ float g_gcli[PADROWS * KCLI];   // gathered normalized phi_cli
static __device__ int   g_rows[NROWS];            // global slot -> original row
static __device__ int   g_cnt[3], g_off[3], g_cursor[3];
static __device__ int   g_cid[NROWS], g_slot[NROWS];
static __device__ unsigned long long g_min6[6];

__device__ __forceinline__ unsigned f2o(float f) {
    unsigned u = __float_as_uint(f);
    return (u & 0x80000000u) ? ~u : (u | 0x80000000u);
}
__device__ __forceinline__ float o2f(unsigned o) {
    unsigned u = (o & 0x80000000u) ? (o & 0x7fffffffu) : ~o;
    return __uint_as_float(u);
}
#define INF_KEY 0xFF80000000000000ull

__device__ __constant__ int c_cA[3] = {0, 0, 1};
__device__ __constant__ int c_cB[3] = {1, 2, 2};

// ---------------------------------------------------------------------------
__global__ void prep_kernel(const int* __restrict__ tw, const int* __restrict__ trw) {
    __shared__ int acc[256];
    int tid = threadIdx.x;
    if (tid < 6) g_min6[tid] = INF_KEY;
    if (tid < 3) g_cnt[tid] = 0;

    // int64 vs int32 layout detection (t values in [0,3))
    int o = 0;
    for (int i = tid; i < NROWS; i += 256) o |= tw[2 * i + 1];
    acc[tid] = o;
    __syncthreads();
    for (int s = 128; s > 0; s >>= 1) {
        if (tid < s) acc[tid] |= acc[tid + s];
        __syncthreads();
    }
    bool is64 = (acc[0] == 0);

    for (int i = tid; i < NROWS; i += 256) {
        int t1 = is64 ? tw[4 * i + 2] : tw[2 * i + 1];
        int tr = is64 ? trw[2 * i]    : trw[i];
        int c = -1;
        if (t1 == 0 && tr == 1) c = 0;
        else if (t1 == 1)       c = 1;
        else if (t1 == 2)       c = 2;
        g_cid[i] = c;
        if (c >= 0) atomicAdd(&g_cnt[c], 1);
    }
    __syncthreads();

    if (tid == 0) {
        g_off[0] = 0; g_off[1] = g_cnt[0]; g_off[2] = g_cnt[0] + g_cnt[1];
        g_cursor[0] = g_off[0]; g_cursor[1] = g_off[1]; g_cursor[2] = g_off[2];
    }
    __syncthreads();

    for (int i = tid; i < NROWS; i += 256) {
        int c = g_cid[i];
        if (c >= 0) {
            int s2 = atomicAdd(&g_cursor[c], 1);
            g_rows[s2] = i;
            g_slot[i] = s2;
        }
    }
}

// ---------------------------------------------------------------------------
__global__ void norm_gather(const float* __restrict__ im, const float* __restrict__ cli) {
    int row = blockIdx.x;
    int c = g_cid[row];
    if (c < 0) return;
    int slot = g_slot[row];
    int tid = threadIdx.x;
    __shared__ float red[256];

    float4 v = ((const float4*)(im + (size_t)row * KDIM))[tid];
    red[tid] = v.x * v.x + v.y * v.y + v.z * v.z + v.w * v.w;
    __syncthreads();
    for (int s = 128; s > 0; s >>= 1) {
        if (tid < s) red[tid] += red[tid + s];
        __syncthreads();
    }
    float inv = 1.0f / fmaxf(sqrtf(red[0]), 1e-12f);
    ((float4*)(g_gim + (size_t)slot * KDIM))[tid] =
        make_float4(v.x * inv, v.y * inv, v.z * inv, v.w * inv);
    __syncthreads();

    float cv = (tid < KCLI) ? cli[row * KCLI + tid] : 0.0f;
    red[tid] = cv * cv;
    __syncthreads();
    for (int s = 128; s > 0; s >>= 1) {
        if (tid < s) red[tid] += red[tid + s];
        __syncthreads();
    }
    float inv2 = 1.0f / fmaxf(sqrtf(red[0]), 1e-12f);
    if (tid < KCLI) g_gcli[slot * KCLI + tid] = cv * inv2;
}

// ---------------------------------------------------------------------------
__global__ void zero_out(float* __restrict__ out, int n) {
    int stride = gridDim.x * blockDim.x;
    int n4 = n / 4;
    for (int i = blockIdx.x * blockDim.x + threadIdx.x; i < n4; i += stride)
        ((float4*)out)[i] = make_float4(0.f, 0.f, 0.f, 0.f);
    int tail = n4 * 4 + blockIdx.x * blockDim.x + threadIdx.x;
    if (tail < n) out[tail] = 0.f;
}

// ---------------------------------------------------------------------------
// 128x64 tile, 8x4 micro, 256 threads, BK=16, prefetch-pipelined global loads.
// ---------------------------------------------------------------------------
__device__ __forceinline__ void tile_gemm(
    const float* __restrict__ A, const float* __restrict__ B, int K,
    int kbeg, int kend, float (&acc)[8][4],
    float (*As)[128], float (*Bs)[64], int tid)
{
    const int lr  = tid >> 2;        // 0..63  (A rows lr, lr+64; B row lr)
    const int lk  = (tid & 3) * 4;   // k offset 0,4,8,12
    const int tx = tid & 15;         // col group (4 cols)
    const int ty = tid >> 4;         // row group (8 rows)

    // prefetch first tile
    float4 a0 = *(const float4*)&A[(size_t)lr        * K + kbeg + lk];
    float4 a1 = *(const float4*)&A[(size_t)(lr + 64) * K + kbeg + lk];
    float4 b0 = *(const float4*)&B[(size_t)lr        * K + kbeg + lk];

    for (int kt = kbeg; kt < kend; kt += 16) {
        __syncthreads();
        As[lk + 0][lr] = a0.x; As[lk + 1][lr] = a0.y;
        As[lk + 2][lr] = a0.z; As[lk + 3][lr] = a0.w;
        As[lk + 0][lr + 64] = a1.x; As[lk + 1][lr + 64] = a1.y;
        As[lk + 2][lr + 64] = a1.z; As[lk + 3][lr + 64] = a1.w;
        Bs[lk + 0][lr] = b0.x; Bs[lk + 1][lr] = b0.y;
        Bs[lk + 2][lr] = b0.z; Bs[lk + 3][lr] = b0.w;
        __syncthreads();

        // prefetch next tile while computing this one
        if (kt + 16 < kend) {
            a0 = *(const float4*)&A[(size_t)lr        * K + kt + 16 + lk];
            a1 = *(const float4*)&A[(size_t)(lr + 64) * K + kt + 16 + lk];
            b0 = *(const float4*)&B[(size_t)lr        * K + kt + 16 + lk];
        }

#pragma unroll
        for (int k = 0; k < 16; k++) {
            float4 ar0 = *(const float4*)&As[k][ty * 8];
            float4 ar1 = *(const float4*)&As[k][ty * 8 + 4];
            float4 br  = *(const float4*)&Bs[k][tx * 4];
            float a[8] = {ar0.x, ar0.y, ar0.z, ar0.w, ar1.x, ar1.y, ar1.z, ar1.w};
            float b[4] = {br.x, br.y, br.z, br.w};
#pragma unroll
            for (int i = 0; i < 8; i++)
#pragma unroll
                for (int j = 0; j < 4; j++) acc[i][j] = fmaf(a[i], b[j], acc[i][j]);
        }
    }
}

// ---------------------------------------------------------------------------
// z in [0,6): im GEMM, combo=z>>1, split=z&1 -> atomicAdd into zeroed out.
//   Exactly 2 addends per zeroed cell => bitwise deterministic (fp add commutes).
// z in [6,9): cli GEMM (K=64) -> direct store + argmin.
// Grid covers worst-case class sizes (2048); excess blocks early-exit.
// ---------------------------------------------------------------------------
__global__ __launch_bounds__(256)
void gemm_all(float* __restrict__ out) {
    __shared__ float As[16][128];
    __shared__ float Bs[16][64];
    const int tid = threadIdx.x;
    const int z = blockIdx.z;
    const int bx = blockIdx.x, by = blockIdx.y;
    const int tx = tid & 15, ty = tid >> 4;

    float acc[8][4];
#pragma unroll
    for (int i = 0; i < 8; i++)
#pragma unroll
        for (int j = 0; j < 4; j++) acc[i][j] = 0.0f;

    if (z < 6) {
        const int combo = z >> 1, split = z & 1;
        const int ca = c_cA[combo], cb = c_cB[combo];
        const int na = g_cnt[ca], nb = g_cnt[cb];
        if (by * 128 >= na || bx * 64 >= nb) return;

        const float* A = g_gim + (size_t)(g_off[ca] + by * 128) * KDIM;
        const float* B = g_gim + (size_t)(g_off[cb] + bx * 64) * KDIM;
        tile_gemm(A, B, KDIM, split * 512, split * 512 + 512, acc, As, Bs, tid);

        const int offA = g_off[ca], offB = g_off[cb];
        int gc[4]; bool cv[4];
#pragma unroll
        for (int j = 0; j < 4; j++) {
            int c = bx * 64 + tx * 4 + j;
            cv[j] = c < nb;
            gc[j] = cv[j] ? g_rows[offB + c] : 0;
        }
        float* __restrict__ op = out + (size_t)combo * NROWS * NROWS;
#pragma unroll
        for (int i = 0; i < 8; i++) {
            int r = by * 128 + ty * 8 + i;
            if (r >= na) continue;
            unsigned rbase = (unsigned)g_rows[offA + r] * NROWS;
#pragma unroll
            for (int j = 0; j < 4; j++) {
                if (!cv[j]) continue;
                atomicAdd(&op[rbase + (unsigned)gc[j]], acc[i][j]);
            }
        }
    } else {
        const int combo = z - 6;
        const int ca = c_cA[combo], cb = c_cB[combo];
        const int na = g_cnt[ca], nb = g_cnt[cb];
        if (by * 128 >= na || bx * 64 >= nb) return;

        const float* A = g_gcli + (size_t)(g_off[ca] + by * 128) * KCLI;
        const float* B = g_gcli + (size_t)(g_off[cb] + bx * 64) * KCLI;
        tile_gemm(A, B, KCLI, 0, KCLI, acc, As, Bs, tid);

        const int offA = g_off[ca], offB = g_off[cb];
        int gc[4]; bool cv[4];
#pragma unroll
        for (int j = 0; j < 4; j++) {
            int c = bx * 64 + tx * 4 + j;
            cv[j] = c < nb;
            gc[j] = cv[j] ? g_rows[offB + c] : 0;
        }
        float* __restrict__ op = out + (size_t)(3 + combo) * NROWS * NROWS;
        unsigned long long best = INF_KEY;
#pragma unroll
        for (int i = 0; i < 8; i++) {
            int r = by * 128 + ty * 8 + i;
            if (r >= na) continue;
            unsigned rbase = (unsigned)g_rows[offA + r] * NROWS;
#pragma unroll
            for (int j = 0; j < 4; j++) {
                if (!cv[j]) continue;
                float s = acc[i][j];
                unsigned flat = rbase + (unsigned)gc[j];
                op[flat] = s;
                unsigned long long key = ((unsigned long long)f2o(s) << 32) | flat;
                if (key < best) best = key;
            }
        }
#pragma unroll
        for (int off = 16; off > 0; off >>= 1) {
            unsigned long long o = __shfl_down_sync(0xffffffffu, best, off);
            if (o < best) best = o;
        }
        if ((tid & 31) == 0 && best != INF_KEY)
            atomicMin(&g_min6[3 + combo], best);
    }
}

// ---------------------------------------------------------------------------
// argmin over the summed im-combo cells (reads deterministic final values)
// ---------------------------------------------------------------------------
__global__ __launch_bounds__(256)
void argmin_im(const float* __restrict__ out) {
    const int combo = blockIdx.z;
    const int ca = c_cA[combo], cb = c_cB[combo];
    const int na = g_cnt[ca], nb = g_cnt[cb];
    const int bx = blockIdx.x, by = blockIdx.y;
    if (by * 128 >= na || bx * 128 >= nb) return;

    const int offA = g_off[ca], offB = g_off[cb];
    const int tid = threadIdx.x;
    const int tx = tid & 15, ty = tid >> 4;

    int gc[8]; bool cv[8];
#pragma unroll
    for (int j = 0; j < 8; j++) {
        int c = bx * 128 + tx * 8 + j;
        cv[j] = c < nb;
        gc[j] = cv[j] ? g_rows[offB + c] : 0;
    }

    const float* __restrict__ op = out + (size_t)combo * NROWS * NROWS;
    unsigned long long best = INF_KEY;
#pragma unroll
    for (int i = 0; i < 8; i++) {
        int r = by * 128 + ty * 8 + i;
        if (r >= na) continue;
        unsigned rbase = (unsigned)g_rows[offA + r] * NROWS;
#pragma unroll
        for (int j = 0; j < 8; j++) {
            if (!cv[j]) continue;
            unsigned flat = rbase + (unsigned)gc[j];
            float s = op[flat];
            unsigned long long key = ((unsigned long long)f2o(s) << 32) | flat;
            if (key < best) best = key;
        }
    }
#pragma unroll
    for (int off = 16; off > 0; off >>= 1) {
        unsigned long long o = __shfl_down_sync(0xffffffffu, best, off);
        if (o < best) best = o;
    }
    if ((tid & 31) == 0 && best != INF_KEY)
        atomicMin(&g_min6[combo], best);
}

// ---------------------------------------------------------------------------
__global__ void finalize_kernel(float* __restrict__ out) {
    int p = threadIdx.x;
    if (p < 6) {
        unsigned long long k = g_min6[p];
        size_t base = (size_t)6 * NROWS * NROWS;
        out[base + p] = o2f((unsigned)(k >> 32));
        unsigned flat = (unsigned)k;
        out[base + 6 + 2 * p]     = (float)(flat / NROWS);
        out[base + 6 + 2 * p + 1] = (float)(flat % NROWS);
    }
}

// ---------------------------------------------------------------------------
extern "C" void kernel_launch(void* const* d_in, const int* in_sizes, int n_in,
                              void* d_out, int out_size) {
    const float* phi_im  = (const float*)d_in[0];
    const float* phi_cli = (const float*)d_in[1];
    const int*   tw      = (const int*)d_in[2];
    const int*   trw     = (const int*)d_in[3];
    float* out = (float*)d_out;

    prep_kernel<<<1, 256>>>(tw, trw);
    norm_gather<<<NROWS, 256>>>(phi_im, phi_cli);
    zero_out<<<2048, 256>>>(out, out_size);

    // Full worst-case coverage: x = 2048/64 = 32, y = 2048/128 = 16.
    // Out-of-range blocks early-exit on g_cnt (cheap).
    dim3 ggrid(32, 16, 9);
    gemm_all<<<ggrid, 256>>>(out);

    dim3 agrid(16, 16, 3);
    argmin_im<<<agrid, 256>>>(out);

    finalize_kernel<<<1, 32>>>(out);
}

// round 12
// speedup vs baseline: 2.1491x; 1.0128x over previous
#include <cuda_runtime.h>

#define NROWS 2048
#define KDIM  1024
#define KCLI  64
#define PADROWS (NROWS + 128)   // tile loader may over-read past last class

// -------- device scratch (statics kept at the ~9.5MB profile) ----
static __device__ float g_gim[PADROWS * KDIM];    // gathered normalized phi_im
static __device__ float g_gcli[PADROWS * KCLI];   // gathered normalized phi_cli
static __device__ int   g_rows[NROWS];            // global slot -> original row
static __device__ int   g_cnt[3], g_off[3], g_cursor[3];
static __device__ int   g_cid[NROWS], g_slot[NROWS];
static __device__ unsigned long long g_min6[6];

__device__ __forceinline__ unsigned f2o(float f) {
    unsigned u = __float_as_uint(f);
    return (u & 0x80000000u) ? ~u : (u | 0x80000000u);
}
__device__ __forceinline__ float o2f(unsigned o) {
    unsigned u = (o & 0x80000000u) ? (o & 0x7fffffffu) : ~o;
    return __uint_as_float(u);
}
#define INF_KEY 0xFF80000000000000ull

__device__ __constant__ int c_cA[3] = {0, 0, 1};
__device__ __constant__ int c_cB[3] = {1, 2, 2};

// ---------------------------------------------------------------------------
__global__ void prep_kernel(const int* __restrict__ tw, const int* __restrict__ trw) {
    __shared__ int acc[256];
    int tid = threadIdx.x;
    if (tid < 6) g_min6[tid] = INF_KEY;
    if (tid < 3) g_cnt[tid] = 0;

    // int64 vs int32 layout detection (t values in [0,3))
    int o = 0;
    for (int i = tid; i < NROWS; i += 256) o |= tw[2 * i + 1];
    acc[tid] = o;
    __syncthreads();
    for (int s = 128; s > 0; s >>= 1) {
        if (tid < s) acc[tid] |= acc[tid + s];
        __syncthreads();
    }
    bool is64 = (acc[0] == 0);

    for (int i = tid; i < NROWS; i += 256) {
        int t1 = is64 ? tw[4 * i + 2] : tw[2 * i + 1];
        int tr = is64 ? trw[2 * i]    : trw[i];
        int c = -1;
        if (t1 == 0 && tr == 1) c = 0;
        else if (t1 == 1)       c = 1;
        else if (t1 == 2)       c = 2;
        g_cid[i] = c;
        if (c >= 0) atomicAdd(&g_cnt[c], 1);
    }
    __syncthreads();

    if (tid == 0) {
        g_off[0] = 0; g_off[1] = g_cnt[0]; g_off[2] = g_cnt[0] + g_cnt[1];
        g_cursor[0] = g_off[0]; g_cursor[1] = g_off[1]; g_cursor[2] = g_off[2];
    }
    __syncthreads();

    for (int i = tid; i < NROWS; i += 256) {
        int c = g_cid[i];
        if (c >= 0) {
            int s2 = atomicAdd(&g_cursor[c], 1);
            g_rows[s2] = i;
            g_slot[i] = s2;
        }
    }
}

// ---------------------------------------------------------------------------
__global__ void norm_gather(const float* __restrict__ im, const float* __restrict__ cli) {
    int row = blockIdx.x;
    int c = g_cid[row];
    if (c < 0) return;
    int slot = g_slot[row];
    int tid = threadIdx.x;
    __shared__ float red[256];

    float4 v = ((const float4*)(im + (size_t)row * KDIM))[tid];
    red[tid] = v.x * v.x + v.y * v.y + v.z * v.z + v.w * v.w;
    __syncthreads();
    for (int s = 128; s > 0; s >>= 1) {
        if (tid < s) red[tid] += red[tid + s];
        __syncthreads();
    }
    float inv = 1.0f / fmaxf(sqrtf(red[0]), 1e-12f);
    ((float4*)(g_gim + (size_t)slot * KDIM))[tid] =
        make_float4(v.x * inv, v.y * inv, v.z * inv, v.w * inv);
    __syncthreads();

    float cv = (tid < KCLI) ? cli[row * KCLI + tid] : 0.0f;
    red[tid] = cv * cv;
    __syncthreads();
    for (int s = 128; s > 0; s >>= 1) {
        if (tid < s) red[tid] += red[tid + s];
        __syncthreads();
    }
    float inv2 = 1.0f / fmaxf(sqrtf(red[0]), 1e-12f);
    if (tid < KCLI) g_gcli[slot * KCLI + tid] = cv * inv2;
}

// ---------------------------------------------------------------------------
__global__ void zero_out(float* __restrict__ out, int n) {
    int stride = gridDim.x * blockDim.x;
    int n4 = n / 4;
    for (int i = blockIdx.x * blockDim.x + threadIdx.x; i < n4; i += stride)
        ((float4*)out)[i] = make_float4(0.f, 0.f, 0.f, 0.f);
    int tail = n4 * 4 + blockIdx.x * blockDim.x + threadIdx.x;
    if (tail < n) out[tail] = 0.f;
}

// ---------------------------------------------------------------------------
// 128x64 tile, 8x4 micro, 256 threads, BK=16.
// DOUBLE-BUFFERED smem: one __syncthreads per k-tile; prefetch LDG overlaps
// compute; STS targets the idle buffer (no read/write hazard between barriers).
// ---------------------------------------------------------------------------
__device__ __forceinline__ void tile_gemm(
    const float* __restrict__ A, const float* __restrict__ B, int K,
    int kbeg, int kend, float (&acc)[8][4],
    float (*As)[16][128], float (*Bs)[16][64], int tid)
{
    const int lr = tid >> 2;        // 0..63  (A rows lr, lr+64; B row lr)
    const int lk = (tid & 3) * 4;   // k offset 0,4,8,12
    const int tx = tid & 15;        // col group (4 cols)
    const int ty = tid >> 4;        // row group (8 rows)

    // load + stage tile 0 into buffer 0
    float4 a0 = *(const float4*)&A[(size_t)lr        * K + kbeg + lk];
    float4 a1 = *(const float4*)&A[(size_t)(lr + 64) * K + kbeg + lk];
    float4 b0 = *(const float4*)&B[(size_t)lr        * K + kbeg + lk];
    As[0][lk + 0][lr] = a0.x; As[0][lk + 1][lr] = a0.y;
    As[0][lk + 2][lr] = a0.z; As[0][lk + 3][lr] = a0.w;
    As[0][lk + 0][lr + 64] = a1.x; As[0][lk + 1][lr + 64] = a1.y;
    As[0][lk + 2][lr + 64] = a1.z; As[0][lk + 3][lr + 64] = a1.w;
    Bs[0][lk + 0][lr] = b0.x; Bs[0][lk + 1][lr] = b0.y;
    Bs[0][lk + 2][lr] = b0.z; Bs[0][lk + 3][lr] = b0.w;
    __syncthreads();

    int buf = 0;
    for (int kt = kbeg; kt < kend; kt += 16) {
        const bool more = (kt + 16 < kend);
        if (more) {   // prefetch next tile; latency hidden under compute below
            a0 = *(const float4*)&A[(size_t)lr        * K + kt + 16 + lk];
            a1 = *(const float4*)&A[(size_t)(lr + 64) * K + kt + 16 + lk];
            b0 = *(const float4*)&B[(size_t)lr        * K + kt + 16 + lk];
        }

#pragma unroll
        for (int k = 0; k < 16; k++) {
            float4 ar0 = *(const float4*)&As[buf][k][ty * 8];
            float4 ar1 = *(const float4*)&As[buf][k][ty * 8 + 4];
            float4 br  = *(const float4*)&Bs[buf][k][tx * 4];
            float a[8] = {ar0.x, ar0.y, ar0.z, ar0.w, ar1.x, ar1.y, ar1.z, ar1.w};
            float b[4] = {br.x, br.y, br.z, br.w};
#pragma unroll
            for (int i = 0; i < 8; i++)
#pragma unroll
                for (int j = 0; j < 4; j++) acc[i][j] = fmaf(a[i], b[j], acc[i][j]);
        }

        if (more) {   // stage next tile into the other buffer
            const int nb = buf ^ 1;
            As[nb][lk + 0][lr] = a0.x; As[nb][lk + 1][lr] = a0.y;
            As[nb][lk + 2][lr] = a0.z; As[nb][lk + 3][lr] = a0.w;
            As[nb][lk + 0][lr + 64] = a1.x; As[nb][lk + 1][lr + 64] = a1.y;
            As[nb][lk + 2][lr + 64] = a1.z; As[nb][lk + 3][lr + 64] = a1.w;
            Bs[nb][lk + 0][lr] = b0.x; Bs[nb][lk + 1][lr] = b0.y;
            Bs[nb][lk + 2][lr] = b0.z; Bs[nb][lk + 3][lr] = b0.w;
            __syncthreads();
            buf = nb;
        }
    }
}

// ---------------------------------------------------------------------------
// z in [0,6): im GEMM, combo=z>>1, split=z&1 -> atomicAdd into zeroed out.
//   Exactly 2 addends per zeroed cell => bitwise deterministic (fp add commutes).
// z in [6,9): cli GEMM (K=64) -> direct store + argmin.
// Grid covers worst-case class sizes (2048); excess blocks early-exit.
// ---------------------------------------------------------------------------
__global__ __launch_bounds__(256, 3)
void gemm_all(float* __restrict__ out) {
    __shared__ float As[2][16][128];
    __shared__ float Bs[2][16][64];
    const int tid = threadIdx.x;
    const int z = blockIdx.z;
    const int bx = blockIdx.x, by = blockIdx.y;
    const int tx = tid & 15, ty = tid >> 4;

    float acc[8][4];
#pragma unroll
    for (int i = 0; i < 8; i++)
#pragma unroll
        for (int j = 0; j < 4; j++) acc[i][j] = 0.0f;

    if (z < 6) {
        const int combo = z >> 1, split = z & 1;
        const int ca = c_cA[combo], cb = c_cB[combo];
        const int na = g_cnt[ca], nb = g_cnt[cb];
        if (by * 128 >= na || bx * 64 >= nb) return;

        const float* A = g_gim + (size_t)(g_off[ca] + by * 128) * KDIM;
        const float* B = g_gim + (size_t)(g_off[cb] + bx * 64) * KDIM;
        tile_gemm(A, B, KDIM, split * 512, split * 512 + 512, acc, As, Bs, tid);

        const int offA = g_off[ca], offB = g_off[cb];
        int gc[4]; bool cv[4];
#pragma unroll
        for (int j = 0; j < 4; j++) {
            int c = bx * 64 + tx * 4 + j;
            cv[j] = c < nb;
            gc[j] = cv[j] ? g_rows[offB + c] : 0;
        }
        float* __restrict__ op = out + (size_t)combo * NROWS * NROWS;
#pragma unroll
        for (int i = 0; i < 8; i++) {
            int r = by * 128 + ty * 8 + i;
            if (r >= na) continue;
            unsigned rbase = (unsigned)g_rows[offA + r] * NROWS;
#pragma unroll
            for (int j = 0; j < 4; j++) {
                if (!cv[j]) continue;
                atomicAdd(&op[rbase + (unsigned)gc[j]], acc[i][j]);
            }
        }
    } else {
        const int combo = z - 6;
        const int ca = c_cA[combo], cb = c_cB[combo];
        const int na = g_cnt[ca], nb = g_cnt[cb];
        if (by * 128 >= na || bx * 64 >= nb) return;

        const float* A = g_gcli + (size_t)(g_off[ca] + by * 128) * KCLI;
        const float* B = g_gcli + (size_t)(g_off[cb] + bx * 64) * KCLI;
        tile_gemm(A, B, KCLI, 0, KCLI, acc, As, Bs, tid);

        const int offA = g_off[ca], offB = g_off[cb];
        int gc[4]; bool cv[4];
#pragma unroll
        for (int j = 0; j < 4; j++) {
            int c = bx * 64 + tx * 4 + j;
            cv[j] = c < nb;
            gc[j] = cv[j] ? g_rows[offB + c] : 0;
        }
        float* __restrict__ op = out + (size_t)(3 + combo) * NROWS * NROWS;
        unsigned long long best = INF_KEY;
#pragma unroll
        for (int i = 0; i < 8; i++) {
            int r = by * 128 + ty * 8 + i;
            if (r >= na) continue;
            unsigned rbase = (unsigned)g_rows[offA + r] * NROWS;
#pragma unroll
            for (int j = 0; j < 4; j++) {
                if (!cv[j]) continue;
                float s = acc[i][j];
                unsigned flat = rbase + (unsigned)gc[j];
                op[flat] = s;
                unsigned long long key = ((unsigned long long)f2o(s) << 32) | flat;
                if (key < best) best = key;
            }
        }
#pragma unroll
        for (int off = 16; off > 0; off >>= 1) {
            unsigned long long o = __shfl_down_sync(0xffffffffu, best, off);
            if (o < best) best = o;
        }
        if ((tid & 31) == 0 && best != INF_KEY)
            atomicMin(&g_min6[3 + combo], best);
    }
}

// ---------------------------------------------------------------------------
// argmin over the summed im-combo cells (reads deterministic final values)
// ---------------------------------------------------------------------------
__global__ __launch_bounds__(256)
void argmin_im(const float* __restrict__ out) {
    const int combo = blockIdx.z;
    const int ca = c_cA[combo], cb = c_cB[combo];
    const int na = g_cnt[ca], nb = g_cnt[cb];
    const int bx = blockIdx.x, by = blockIdx.y;
    if (by * 128 >= na || bx * 128 >= nb) return;

    const int offA = g_off[ca], offB = g_off[cb];
    const int tid = threadIdx.x;
    const int tx = tid & 15, ty = tid >> 4;

    int gc[8]; bool cv[8];
#pragma unroll
    for (int j = 0; j < 8; j++) {
        int c = bx * 128 + tx * 8 + j;
        cv[j] = c < nb;
        gc[j] = cv[j] ? g_rows[offB + c] : 0;
    }

    const float* __restrict__ op = out + (size_t)combo * NROWS * NROWS;
    unsigned long long best = INF_KEY;
#pragma unroll
    for (int i = 0; i < 8; i++) {
        int r = by * 128 + ty * 8 + i;
        if (r >= na) continue;
        unsigned rbase = (unsigned)g_rows[offA + r] * NROWS;
#pragma unroll
        for (int j = 0; j < 8; j++) {
            if (!cv[j]) continue;
            unsigned flat = rbase + (unsigned)gc[j];
            float s = op[flat];
            unsigned long long key = ((unsigned long long)f2o(s) << 32) | flat;
            if (key < best) best = key;
        }
    }
#pragma unroll
    for (int off = 16; off > 0; off >>= 1) {
        unsigned long long o = __shfl_down_sync(0xffffffffu, best, off);
        if (o < best) best = o;
    }
    if ((tid & 31) == 0 && best != INF_KEY)
        atomicMin(&g_min6[combo], best);
}

// ---------------------------------------------------------------------------
__global__ void finalize_kernel(float* __restrict__ out) {
    int p = threadIdx.x;
    if (p < 6) {
        unsigned long long k = g_min6[p];
        size_t base = (size_t)6 * NROWS * NROWS;
        out[base + p] = o2f((unsigned)(k >> 32));
        unsigned flat = (unsigned)k;
        out[base + 6 + 2 * p]     = (float)(flat / NROWS);
        out[base + 6 + 2 * p + 1] = (float)(flat % NROWS);
    }
}

// ---------------------------------------------------------------------------
extern "C" void kernel_launch(void* const* d_in, const int* in_sizes, int n_in,
                              void* d_out, int out_size) {
    const float* phi_im  = (const float*)d_in[0];
    const float* phi_cli = (const float*)d_in[1];
    const int*   tw      = (const int*)d_in[2];
    const int*   trw     = (const int*)d_in[3];
    float* out = (float*)d_out;

    prep_kernel<<<1, 256>>>(tw, trw);
    norm_gather<<<NROWS, 256>>>(phi_im, phi_cli);
    zero_out<<<2048, 256>>>(out, out_size);

    // Full worst-case coverage: x = 2048/64 = 32, y = 2048/128 = 16.
    // Out-of-range blocks early-exit on g_cnt (cheap).
    dim3 ggrid(32, 16, 9);
    gemm_all<<<ggrid, 256>>>(out);

    dim3 agrid(16, 16, 3);
    argmin_im<<<agrid, 256>>>(out);

    finalize_kernel<<<1, 32>>>(out);
}

// round 13
// speedup vs baseline: 2.1793x; 1.0141x over previous
#include <cuda_runtime.h>

#define NROWS 2048
#define KDIM  1024
#define KCLI  64
#define PADROWS (NROWS + 128)   // tile loader may over-read past last class

// -------- device scratch (statics kept at the ~9.5MB profile) ----
static __device__ float g_gim[PADROWS * KDIM];    // gathered normalized phi_im
static __device__ float g_gcli[PADROWS * KCLI];   // gathered normalized phi_cli
static __device__ int   g_rows[NROWS];            // global slot -> original row
static __device__ int   g_cnt[3], g_off[3], g_cursor[3];
static __device__ int   g_cid[NROWS], g_slot[NROWS];
static __device__ unsigned long long g_min6[6];

__device__ __forceinline__ unsigned f2o(float f) {
    unsigned u = __float_as_uint(f);
    return (u & 0x80000000u) ? ~u : (u | 0x80000000u);
}
__device__ __forceinline__ float o2f(unsigned o) {
    unsigned u = (o & 0x80000000u) ? (o & 0x7fffffffu) : ~o;
    return __uint_as_float(u);
}
#define INF_KEY 0xFF80000000000000ull

__device__ __constant__ int c_cA[3] = {0, 0, 1};
__device__ __constant__ int c_cB[3] = {1, 2, 2};

// packed f32x2 helpers (sm_103a dual-lane fp32 FMA; only reachable via PTX)
__device__ __forceinline__ unsigned long long pack2(float lo, float hi) {
    unsigned long long r;
    asm("mov.b64 %0, {%1, %2};" : "=l"(r) : "f"(lo), "f"(hi));
    return r;
}
__device__ __forceinline__ void fma2(unsigned long long& d,
                                     unsigned long long a, unsigned long long b) {
    asm("fma.rn.f32x2 %0, %1, %2, %0;" : "+l"(d) : "l"(a), "l"(b));
}
__device__ __forceinline__ void unpack2(unsigned long long v, float& lo, float& hi) {
    asm("mov.b64 {%0, %1}, %2;" : "=f"(lo), "=f"(hi) : "l"(v));
}

// ---------------------------------------------------------------------------
__global__ void prep_kernel(const int* __restrict__ tw, const int* __restrict__ trw) {
    __shared__ int acc[256];
    int tid = threadIdx.x;
    if (tid < 6) g_min6[tid] = INF_KEY;
    if (tid < 3) g_cnt[tid] = 0;

    // int64 vs int32 layout detection (t values in [0,3))
    int o = 0;
    for (int i = tid; i < NROWS; i += 256) o |= tw[2 * i + 1];
    acc[tid] = o;
    __syncthreads();
    for (int s = 128; s > 0; s >>= 1) {
        if (tid < s) acc[tid] |= acc[tid + s];
        __syncthreads();
    }
    bool is64 = (acc[0] == 0);

    for (int i = tid; i < NROWS; i += 256) {
        int t1 = is64 ? tw[4 * i + 2] : tw[2 * i + 1];
        int tr = is64 ? trw[2 * i]    : trw[i];
        int c = -1;
        if (t1 == 0 && tr == 1) c = 0;
        else if (t1 == 1)       c = 1;
        else if (t1 == 2)       c = 2;
        g_cid[i] = c;
        if (c >= 0) atomicAdd(&g_cnt[c], 1);
    }
    __syncthreads();

    if (tid == 0) {
        g_off[0] = 0; g_off[1] = g_cnt[0]; g_off[2] = g_cnt[0] + g_cnt[1];
        g_cursor[0] = g_off[0]; g_cursor[1] = g_off[1]; g_cursor[2] = g_off[2];
    }
    __syncthreads();

    for (int i = tid; i < NROWS; i += 256) {
        int c = g_cid[i];
        if (c >= 0) {
            int s2 = atomicAdd(&g_cursor[c], 1);
            g_rows[s2] = i;
            g_slot[i] = s2;
        }
    }
}

// ---------------------------------------------------------------------------
__global__ void norm_gather(const float* __restrict__ im, const float* __restrict__ cli) {
    int row = blockIdx.x;
    int c = g_cid[row];
    if (c < 0) return;
    int slot = g_slot[row];
    int tid = threadIdx.x;
    __shared__ float red[256];

    float4 v = ((const float4*)(im + (size_t)row * KDIM))[tid];
    red[tid] = v.x * v.x + v.y * v.y + v.z * v.z + v.w * v.w;
    __syncthreads();
    for (int s = 128; s > 0; s >>= 1) {
        if (tid < s) red[tid] += red[tid + s];
        __syncthreads();
    }
    float inv = 1.0f / fmaxf(sqrtf(red[0]), 1e-12f);
    ((float4*)(g_gim + (size_t)slot * KDIM))[tid] =
        make_float4(v.x * inv, v.y * inv, v.z * inv, v.w * inv);
    __syncthreads();

    float cv = (tid < KCLI) ? cli[row * KCLI + tid] : 0.0f;
    red[tid] = cv * cv;
    __syncthreads();
    for (int s = 128; s > 0; s >>= 1) {
        if (tid < s) red[tid] += red[tid + s];
        __syncthreads();
    }
    float inv2 = 1.0f / fmaxf(sqrtf(red[0]), 1e-12f);
    if (tid < KCLI) g_gcli[slot * KCLI + tid] = cv * inv2;
}

// ---------------------------------------------------------------------------
__global__ void zero_out(float* __restrict__ out, int n) {
    int stride = gridDim.x * blockDim.x;
    int n4 = n / 4;
    for (int i = blockIdx.x * blockDim.x + threadIdx.x; i < n4; i += stride)
        ((float4*)out)[i] = make_float4(0.f, 0.f, 0.f, 0.f);
    int tail = n4 * 4 + blockIdx.x * blockDim.x + threadIdx.x;
    if (tail < n) out[tail] = 0.f;
}

// ---------------------------------------------------------------------------
// 128x64 tile, 8x4 micro (as 4x4 f32x2 pairs over i), 256 threads, BK=16.
// Double-buffered smem; inner loop uses fma.rn.f32x2 (2 fp32 FMA lanes/op).
// A-operand pairs come free from LDS.128 (adjacent i); B is duplicated into
// both lanes (4 packs per k-step).
// ---------------------------------------------------------------------------
__device__ __forceinline__ void tile_gemm(
    const float* __restrict__ A, const float* __restrict__ B, int K,
    int kbeg, int kend, unsigned long long (&acc2)[4][4],
    float (*As)[16][128], float (*Bs)[16][64], int tid)
{
    const int lr = tid >> 2;        // 0..63  (A rows lr, lr+64; B row lr)
    const int lk = (tid & 3) * 4;   // k offset 0,4,8,12
    const int tx = tid & 15;        // col group (4 cols)
    const int ty = tid >> 4;        // row group (8 rows)

    // load + stage tile 0 into buffer 0
    float4 a0 = *(const float4*)&A[(size_t)lr        * K + kbeg + lk];
    float4 a1 = *(const float4*)&A[(size_t)(lr + 64) * K + kbeg + lk];
    float4 b0 = *(const float4*)&B[(size_t)lr        * K + kbeg + lk];
    As[0][lk + 0][lr] = a0.x; As[0][lk + 1][lr] = a0.y;
    As[0][lk + 2][lr] = a0.z; As[0][lk + 3][lr] = a0.w;
    As[0][lk + 0][lr + 64] = a1.x; As[0][lk + 1][lr + 64] = a1.y;
    As[0][lk + 2][lr + 64] = a1.z; As[0][lk + 3][lr + 64] = a1.w;
    Bs[0][lk + 0][lr] = b0.x; Bs[0][lk + 1][lr] = b0.y;
    Bs[0][lk + 2][lr] = b0.z; Bs[0][lk + 3][lr] = b0.w;
    __syncthreads();

    int buf = 0;
    for (int kt = kbeg; kt < kend; kt += 16) {
        const bool more = (kt + 16 < kend);
        if (more) {   // prefetch next tile; latency hidden under compute below
            a0 = *(const float4*)&A[(size_t)lr        * K + kt + 16 + lk];
            a1 = *(const float4*)&A[(size_t)(lr + 64) * K + kt + 16 + lk];
            b0 = *(const float4*)&B[(size_t)lr        * K + kt + 16 + lk];
        }

#pragma unroll
        for (int k = 0; k < 16; k++) {
            // a pairs: 4 x f32x2 straight from shared (adjacent i values)
            const ulonglong2* ap =
                (const ulonglong2*)&As[buf][k][ty * 8];      // 32B-aligned
            ulonglong2 av0 = ap[0], av1 = ap[1];
            unsigned long long a2[4] = {av0.x, av0.y, av1.x, av1.y};
            float4 br = *(const float4*)&Bs[buf][k][tx * 4];
            unsigned long long bb[4] = {
                pack2(br.x, br.x), pack2(br.y, br.y),
                pack2(br.z, br.z), pack2(br.w, br.w)};
#pragma unroll
            for (int i2 = 0; i2 < 4; i2++)
#pragma unroll
                for (int j = 0; j < 4; j++)
                    fma2(acc2[i2][j], a2[i2], bb[j]);
        }

        if (more) {   // stage next tile into the other buffer
            const int nb = buf ^ 1;
            As[nb][lk + 0][lr] = a0.x; As[nb][lk + 1][lr] = a0.y;
            As[nb][lk + 2][lr] = a0.z; As[nb][lk + 3][lr] = a0.w;
            As[nb][lk + 0][lr + 64] = a1.x; As[nb][lk + 1][lr + 64] = a1.y;
            As[nb][lk + 2][lr + 64] = a1.z; As[nb][lk + 3][lr + 64] = a1.w;
            Bs[nb][lk + 0][lr] = b0.x; Bs[nb][lk + 1][lr] = b0.y;
            Bs[nb][lk + 2][lr] = b0.z; Bs[nb][lk + 3][lr] = b0.w;
            __syncthreads();
            buf = nb;
        }
    }
}

__device__ __forceinline__ void unpack_acc(
    const unsigned long long (&acc2)[4][4], float (&acc)[8][4])
{
#pragma unroll
    for (int i2 = 0; i2 < 4; i2++)
#pragma unroll
        for (int j = 0; j < 4; j++)
            unpack2(acc2[i2][j], acc[2 * i2][j], acc[2 * i2 + 1][j]);
}

// ---------------------------------------------------------------------------
// z in [0,6): im GEMM, combo=z>>1, split=z&1 -> atomicAdd into zeroed out.
//   Exactly 2 addends per zeroed cell => bitwise deterministic (fp add commutes).
// z in [6,9): cli GEMM (K=64) -> direct store + argmin.
// Grid covers worst-case class sizes (2048); excess blocks early-exit.
// ---------------------------------------------------------------------------
__global__ __launch_bounds__(256, 3)
void gemm_all(float* __restrict__ out) {
    __shared__ float As[2][16][128];
    __shared__ float Bs[2][16][64];
    const int tid = threadIdx.x;
    const int z = blockIdx.z;
    const int bx = blockIdx.x, by = blockIdx.y;
    const int tx = tid & 15, ty = tid >> 4;

    unsigned long long acc2[4][4];
#pragma unroll
    for (int i = 0; i < 4; i++)
#pragma unroll
        for (int j = 0; j < 4; j++) acc2[i][j] = 0ull;
    float acc[8][4];

    if (z < 6) {
        const int combo = z >> 1, split = z & 1;
        const int ca = c_cA[combo], cb = c_cB[combo];
        const int na = g_cnt[ca], nb = g_cnt[cb];
        if (by * 128 >= na || bx * 64 >= nb) return;

        const float* A = g_gim + (size_t)(g_off[ca] + by * 128) * KDIM;
        const float* B = g_gim + (size_t)(g_off[cb] + bx * 64) * KDIM;
        tile_gemm(A, B, KDIM, split * 512, split * 512 + 512, acc2, As, Bs, tid);
        unpack_acc(acc2, acc);

        const int offA = g_off[ca], offB = g_off[cb];
        int gc[4]; bool cv[4];
#pragma unroll
        for (int j = 0; j < 4; j++) {
            int c = bx * 64 + tx * 4 + j;
            cv[j] = c < nb;
            gc[j] = cv[j] ? g_rows[offB + c] : 0;
        }
        float* __restrict__ op = out + (size_t)combo * NROWS * NROWS;
#pragma unroll
        for (int i = 0; i < 8; i++) {
            int r = by * 128 + ty * 8 + i;
            if (r >= na) continue;
            unsigned rbase = (unsigned)g_rows[offA + r] * NROWS;
#pragma unroll
            for (int j = 0; j < 4; j++) {
                if (!cv[j]) continue;
                atomicAdd(&op[rbase + (unsigned)gc[j]], acc[i][j]);
            }
        }
    } else {
        const int combo = z - 6;
        const int ca = c_cA[combo], cb = c_cB[combo];
        const int na = g_cnt[ca], nb = g_cnt[cb];
        if (by * 128 >= na || bx * 64 >= nb) return;

        const float* A = g_gcli + (size_t)(g_off[ca] + by * 128) * KCLI;
        const float* B = g_gcli + (size_t)(g_off[cb] + bx * 64) * KCLI;
        tile_gemm(A, B, KCLI, 0, KCLI, acc2, As, Bs, tid);
        unpack_acc(acc2, acc);

        const int offA = g_off[ca], offB = g_off[cb];
        int gc[4]; bool cv[4];
#pragma unroll
        for (int j = 0; j < 4; j++) {
            int c = bx * 64 + tx * 4 + j;
            cv[j] = c < nb;
            gc[j] = cv[j] ? g_rows[offB + c] : 0;
        }
        float* __restrict__ op = out + (size_t)(3 + combo) * NROWS * NROWS;
        unsigned long long best = INF_KEY;
#pragma unroll
        for (int i = 0; i < 8; i++) {
            int r = by * 128 + ty * 8 + i;
            if (r >= na) continue;
            unsigned rbase = (unsigned)g_rows[offA + r] * NROWS;
#pragma unroll
            for (int j = 0; j < 4; j++) {
                if (!cv[j]) continue;
                float s = acc[i][j];
                unsigned flat = rbase + (unsigned)gc[j];
                op[flat] = s;
                unsigned long long key = ((unsigned long long)f2o(s) << 32) | flat;
                if (key < best) best = key;
            }
        }
#pragma unroll
        for (int off = 16; off > 0; off >>= 1) {
            unsigned long long o = __shfl_down_sync(0xffffffffu, best, off);
            if (o < best) best = o;
        }
        if ((tid & 31) == 0 && best != INF_KEY)
            atomicMin(&g_min6[3 + combo], best);
    }
}

// ---------------------------------------------------------------------------
// argmin over the summed im-combo cells (reads deterministic final values)
// ---------------------------------------------------------------------------
__global__ __launch_bounds__(256)
void argmin_im(const float* __restrict__ out) {
    const int combo = blockIdx.z;
    const int ca = c_cA[combo], cb = c_cB[combo];
    const int na = g_cnt[ca], nb = g_cnt[cb];
    const int bx = blockIdx.x, by = blockIdx.y;
    if (by * 128 >= na || bx * 128 >= nb) return;

    const int offA = g_off[ca], offB = g_off[cb];
    const int tid = threadIdx.x;
    const int tx = tid & 15, ty = tid >> 4;

    int gc[8]; bool cv[8];
#pragma unroll
    for (int j = 0; j < 8; j++) {
        int c = bx * 128 + tx * 8 + j;
        cv[j] = c < nb;
        gc[j] = cv[j] ? g_rows[offB + c] : 0;
    }

    const float* __restrict__ op = out + (size_t)combo * NROWS * NROWS;
    unsigned long long best = INF_KEY;
#pragma unroll
    for (int i = 0; i < 8; i++) {
        int r = by * 128 + ty * 8 + i;
        if (r >= na) continue;
        unsigned rbase = (unsigned)g_rows[offA + r] * NROWS;
#pragma unroll
        for (int j = 0; j < 8; j++) {
            if (!cv[j]) continue;
            unsigned flat = rbase + (unsigned)gc[j];
            float s = op[flat];
            unsigned long long key = ((unsigned long long)f2o(s) << 32) | flat;
            if (key < best) best = key;
        }
    }
#pragma unroll
    for (int off = 16; off > 0; off >>= 1) {
        unsigned long long o = __shfl_down_sync(0xffffffffu, best, off);
        if (o < best) best = o;
    }
    if ((tid & 31) == 0 && best != INF_KEY)
        atomicMin(&g_min6[combo], best);
}

// ---------------------------------------------------------------------------
__global__ void finalize_kernel(float* __restrict__ out) {
    int p = threadIdx.x;
    if (p < 6) {
        unsigned long long k = g_min6[p];
        size_t base = (size_t)6 * NROWS * NROWS;
        out[base + p] = o2f((unsigned)(k >> 32));
        unsigned flat = (unsigned)k;
        out[base + 6 + 2 * p]     = (float)(flat / NROWS);
        out[base + 6 + 2 * p + 1] = (float)(flat % NROWS);
    }
}

// ---------------------------------------------------------------------------
extern "C" void kernel_launch(void* const* d_in, const int* in_sizes, int n_in,
                              void* d_out, int out_size) {
    const float* phi_im  = (const float*)d_in[0];
    const float* phi_cli = (const float*)d_in[1];
    const int*   tw      = (const int*)d_in[2];
    const int*   trw     = (const int*)d_in[3];
    float* out = (float*)d_out;

    prep_kernel<<<1, 256>>>(tw, trw);
    norm_gather<<<NROWS, 256>>>(phi_im, phi_cli);
    zero_out<<<2048, 256>>>(out, out_size);

    // Full worst-case coverage: x = 2048/64 = 32, y = 2048/128 = 16.
    // Out-of-range blocks early-exit on g_cnt (cheap).
    dim3 ggrid(32, 16, 9);
    gemm_all<<<ggrid, 256>>>(out);

    dim3 agrid(16, 16, 3);
    argmin_im<<<agrid, 256>>>(out);

    finalize_kernel<<<1, 32>>>(out);
}